// round 16
// baseline (speedup 1.0000x reference)
#include <cuda_runtime.h>
#include <math.h>

#define HH 160
#define WW 320
#define BB 4
#define CCH 64
#define HWP (HH*WW)            // 51200
#define NPIX (BB*CCH*HWP)      // 13107200

// ---------------- scratch: referenced ONLY inside device code -------------------
__device__ __align__(256) float g_on[NPIX];   // out_normal
__device__ __align__(256) float g_wt[NPIX];   // shift-weighted sum
__device__ __align__(256) float g_nn[NPIX];   // new_normal
__device__ __align__(256) float g_x [NPIX];   // conv_rgbd output
__device__ float g_xrow[BB*CCH*HH];
__device__ float g_xcol[BB*CCH*WW];
__device__ float g_qp[BB*CCH*HH];
__device__ float g_kp[BB*CCH*WW];
__device__ float g_m[BB*CCH];
__device__ float g_z[BB*CCH];
__device__ float g_gate[BB*9];
__device__ float g_s[BB*9];
__device__ float g_kd[CCH*CCH];

// ---------------- block reductions (blockDim.x == 256) --------------------------
__device__ __forceinline__ float block_sum_256(float v){
    __shared__ float red[8];
    int tid = threadIdx.x;
#pragma unroll
    for (int o = 16; o > 0; o >>= 1) v += __shfl_xor_sync(0xffffffffu, v, o);
    __syncthreads();
    if ((tid & 31) == 0) red[tid >> 5] = v;
    __syncthreads();
    if (tid == 0){
        float r = 0.f;
#pragma unroll
        for (int i = 0; i < 8; i++) r += red[i];
        red[0] = r;
    }
    __syncthreads();
    return red[0];
}

__device__ __forceinline__ float block_max_256(float v){
    __shared__ float red[8];
    int tid = threadIdx.x;
#pragma unroll
    for (int o = 16; o > 0; o >>= 1) v = fmaxf(v, __shfl_xor_sync(0xffffffffu, v, o));
    __syncthreads();
    if ((tid & 31) == 0) red[tid >> 5] = v;
    __syncthreads();
    if (tid == 0){
        float r = red[0];
#pragma unroll
        for (int i = 1; i < 8; i++) r = fmaxf(r, red[i]);
        red[0] = r;
    }
    __syncthreads();
    return red[0];
}

// ---------------- illumination gate: conv s2 + BN + ReLU -> mean ----------------
__global__ void gate_kernel(const float* __restrict__ illu, const float* __restrict__ tw,
                            const float* __restrict__ tb, const float* __restrict__ bg,
                            const float* __restrict__ bbet, const float* __restrict__ bm,
                            const float* __restrict__ bv){
    const int bn = blockIdx.x;          // b*9+n
    const int b = bn / 9, n = bn % 9;
    const float* src = illu + (size_t)b * (2*HH) * (2*WW);
    float w9[9];
#pragma unroll
    for (int k = 0; k < 9; k++) w9[k] = tw[n*9+k];
    const float bias = tb[n];
    const float sc = bg[n] * rsqrtf(bv[n] + 1e-5f);
    const float sh = bbet[n] - bm[n]*sc;
    float acc = 0.f;
    for (int i = threadIdx.x; i < HWP; i += 256){
        int y = i / WW, x = i - y*WW;
        float c = bias;
#pragma unroll
        for (int ky = 0; ky < 3; ky++){
            int iy = 2*y + ky - 1;
            if ((unsigned)iy >= (unsigned)(2*HH)) continue;
#pragma unroll
            for (int kx = 0; kx < 3; kx++){
                int ix = 2*x + kx - 1;
                if ((unsigned)ix < (unsigned)(2*WW))
                    c = fmaf(src[(size_t)iy*(2*WW)+ix], w9[ky*3+kx], c);
            }
        }
        acc += fmaxf(c*sc + sh, 0.f);
    }
    float total = block_sum_256(acc);
    if (threadIdx.x == 0) g_gate[bn] = total * (1.f / HWP);
}

// ---------------- s normalization + kernel_diff ----------------------------------
__global__ void prep_kernel(const float* __restrict__ conv_w){
    int tid = threadIdx.x;
    if (tid < BB){
        float s = 0.f;
        for (int n = 0; n < 9; n++) s += fabsf(g_gate[tid*9+n]);
        float inv = 1.f / (s + 1e-8f);
        for (int n = 0; n < 9; n++) g_s[tid*9+n] = g_gate[tid*9+n] * inv;
    }
    for (int e = tid; e < CCH*CCH; e += 256){
        float a = 0.f;
#pragma unroll
        for (int k = 0; k < 9; k++) a += conv_w[e*9 + k];
        g_kd[e] = a;
    }
}

// ---------------- tiled 3x3 conv: 16x16 px, 32 co/block ---------------------------
// EPI=false: in = in0 param (guidance), writes g_on.
// EPI=true : channels 0-63 from g_nn (direct), 64-127 from in1 param (lidar); BN+ReLU; writes g_x.
template<int CIN, bool EPI>
__global__ void __launch_bounds__(256) conv3x3_kernel(
    const float* __restrict__ in0, const float* __restrict__ in1,
    const float* __restrict__ wgt, const float* __restrict__ bias,
    const float* __restrict__ bng, const float* __restrict__ bnb,
    const float* __restrict__ bnm, const float* __restrict__ bnv)
{
    __shared__ float s_in[16*18*20];     // [ci][18 rows, row-stride 20]
    __shared__ float s_w[32*16*9];       // [co][ci][k]
    const int tid = threadIdx.x;
    const int x0 = blockIdx.x * 16, y0 = blockIdx.y * 16;
    const int b = blockIdx.z >> 1, co0 = (blockIdx.z & 1) * 32;
    const int co_slot = tid >> 6;        // 0..3
    const int px = tid & 63;
    const int pr = (px >> 3) * 2;        // 0,2,...,14
    const int pc = px & 7;               // 0..7

    float acc[8][2][2];
#pragma unroll
    for (int u = 0; u < 8; u++)
#pragma unroll
        for (int i = 0; i < 2; i++){ acc[u][i][0] = 0.f; acc[u][i][1] = 0.f; }

    for (int cg = 0; cg < CIN/16; cg++){
        const float* src; int cbase;
        if (EPI){   // CIN==128: first 64 ch from g_nn (device symbol), rest from lidar
            if (cg >= 4){ src = in1;  cbase = (cg-4)*16; }
            else        { src = g_nn; cbase = cg*16; }
        } else {
            src = in0; cbase = cg*16;
        }
        for (int e = tid; e < 16*18*18; e += 256){
            int ci = e / 324; int rem = e - ci*324;
            int r = rem / 18, c = rem - r*18;
            int y = y0 - 1 + r, x = x0 - 1 + c;
            float v = 0.f;
            if ((unsigned)y < (unsigned)HH && (unsigned)x < (unsigned)WW)
                v = src[((size_t)(b*CCH + cbase + ci)*HH + y)*WW + x];
            s_in[ci*360 + r*20 + c] = v;
        }
        for (int e = tid; e < 32*16*9; e += 256){
            int co = e / 144; int rem = e - co*144;
            int ci = rem / 9; int k = rem - ci*9;
            s_w[e] = wgt[((size_t)(co0+co)*CIN + cg*16 + ci)*9 + k];
        }
        __syncthreads();
#pragma unroll
        for (int ci = 0; ci < 16; ci++){
            float win[4][6];
            const float* sp = &s_in[ci*360];
#pragma unroll
            for (int r = 0; r < 4; r++){
#pragma unroll
                for (int j = 0; j < 3; j++){
                    win[r][j]   = sp[(pr+r)*20 + pc + j];
                    win[r][j+3] = sp[(pr+r)*20 + pc + 8 + j];
                }
            }
#pragma unroll
            for (int u = 0; u < 8; u++){
                const float* wp = &s_w[((co_slot*8+u)*16 + ci)*9];
                const float w0=wp[0],w1=wp[1],w2=wp[2],w3=wp[3],w4=wp[4],
                            w5=wp[5],w6=wp[6],w7=wp[7],w8=wp[8];
#pragma unroll
                for (int dy = 0; dy < 2; dy++){
#pragma unroll
                    for (int g = 0; g < 2; g++){
                        float a = acc[u][dy][g];
                        a = fmaf(win[dy  ][g*3+0], w0, a);
                        a = fmaf(win[dy  ][g*3+1], w1, a);
                        a = fmaf(win[dy  ][g*3+2], w2, a);
                        a = fmaf(win[dy+1][g*3+0], w3, a);
                        a = fmaf(win[dy+1][g*3+1], w4, a);
                        a = fmaf(win[dy+1][g*3+2], w5, a);
                        a = fmaf(win[dy+2][g*3+0], w6, a);
                        a = fmaf(win[dy+2][g*3+1], w7, a);
                        a = fmaf(win[dy+2][g*3+2], w8, a);
                        acc[u][dy][g] = a;
                    }
                }
            }
        }
        __syncthreads();
    }
    float* outg = EPI ? g_x : g_on;      // device-symbol reference (legal here)
#pragma unroll
    for (int u = 0; u < 8; u++){
        const int co = co0 + co_slot*8 + u;
        float sc = 1.f, sh = 0.f;
        if (EPI){
            sc = bng[co] * rsqrtf(bnv[co] + 1e-5f);
            sh = (bias[co] - bnm[co]) * sc + bnb[co];
        }
#pragma unroll
        for (int dy = 0; dy < 2; dy++){
#pragma unroll
            for (int g = 0; g < 2; g++){
                int y = y0 + pr + dy, x = x0 + pc + 8*g;
                float v = acc[u][dy][g];
                if (EPI) v = fmaxf(v*sc + sh, 0.f);
                outg[((size_t)(b*CCH + co)*HH + y)*WW + x] = v;
            }
        }
    }
}

// ---------------- weighted = sum_n s_n * reflect-shift_n(out_normal) --------------
__global__ void fuse_weighted_kernel(){
    __shared__ float ss[9];
    const int idx = blockIdx.x * 256 + threadIdx.x;
    const int b = idx / (CCH*HWP);       // block-uniform (256 | C*HW)
    if (threadIdx.x < 9) ss[threadIdx.x] = g_s[b*9 + threadIdx.x];
    __syncthreads();
    const int w = idx % WW;
    const int t = idx / WW;
    const int h = t % HH;
    const int bc = t / HH;
    const float* base = g_on + (size_t)bc*HWP;
    float a = 0.f;
#pragma unroll
    for (int n = 0; n < 9; n++){
        int dy = n/3 - 1, dx = n%3 - 1;
        int y = h + dy; y = (y < 0) ? 1 : ((y >= HH) ? HH-2 : y);
        int x = w + dx; x = (x < 0) ? 1 : ((x >= WW) ? WW-2 : x);
        a = fmaf(ss[n], base[y*WW + x], a);
    }
    g_wt[idx] = a;
}

// ---------------- new_normal = out_normal - theta * (kd @ weighted) ----------------
__global__ void __launch_bounds__(256) fuse_gemm_kernel(const float* __restrict__ theta){
    __shared__ __align__(16) float s_t[64*128];
    const int tid = threadIdx.x;
    const int b = blockIdx.y;
    const int px0 = blockIdx.x * 128;
    for (int e = tid; e < 2048; e += 256){
        int c = e >> 5; int p = (e & 31) * 4;
        *(float4*)&s_t[c*128 + p] = *(const float4*)&g_wt[((size_t)(b*CCH + c))*HWP + px0 + p];
    }
    __syncthreads();
    const int co_slot = tid >> 5;        // 0..7 (warp-uniform), 8 co each
    const int ps = (tid & 31) * 4;
    float acc[8][4];
#pragma unroll
    for (int i = 0; i < 8; i++){ acc[i][0]=acc[i][1]=acc[i][2]=acc[i][3]=0.f; }
#pragma unroll 4
    for (int c = 0; c < 64; c++){
        float4 wv = *(const float4*)&s_t[c*128 + ps];
#pragma unroll
        for (int i = 0; i < 8; i++){
            float kv = g_kd[(co_slot*8+i)*64 + c];   // warp-uniform load
            acc[i][0] = fmaf(kv, wv.x, acc[i][0]);
            acc[i][1] = fmaf(kv, wv.y, acc[i][1]);
            acc[i][2] = fmaf(kv, wv.z, acc[i][2]);
            acc[i][3] = fmaf(kv, wv.w, acc[i][3]);
        }
    }
    const float th = theta[0];
#pragma unroll
    for (int i = 0; i < 8; i++){
        int co = co_slot*8 + i;
        size_t base = ((size_t)(b*CCH + co))*HWP + px0 + ps;
        float4 ov = *(const float4*)&g_on[base];
        float4 r;
        r.x = ov.x - th*acc[i][0];
        r.y = ov.y - th*acc[i][1];
        r.z = ov.z - th*acc[i][2];
        r.w = ov.w - th*acc[i][3];
        *(float4*)&g_nn[base] = r;
    }
}

// ---------------- pooled means of x -------------------------------------------------
__global__ void rowmean_kernel(){           // one warp per (b,c,h)
    int r = blockIdx.x * 8 + (threadIdx.x >> 5);
    int lane = threadIdx.x & 31;
    const float* p = g_x + (size_t)r * WW;
    float s = 0.f;
#pragma unroll
    for (int i = 0; i < 10; i++) s += p[lane + i*32];
#pragma unroll
    for (int o = 16; o > 0; o >>= 1) s += __shfl_xor_sync(0xffffffffu, s, o);
    if (lane == 0) g_xrow[r] = s * (1.f / WW);
}

__global__ void colmean_kernel(){           // block per (b,c), 320 threads
    int bc = blockIdx.x;
    int w = threadIdx.x;
    const float* p = g_x + (size_t)bc * HWP + w;
    float s = 0.f;
    for (int h = 0; h < HH; h++) s += p[h*WW];
    g_xcol[bc*WW + w] = s * (1.f / HH);
}

// ---------------- pooled q/k projections (exact: mean commutes with 1x1) ------------
__global__ void qk_pool_kernel(const float* __restrict__ qw, const float* __restrict__ qb,
                               const float* __restrict__ kw, const float* __restrict__ kb){
    const int b = blockIdx.x;
    const bool is_q = (blockIdx.y == 0);
    const int L = is_q ? HH : WW;
    const float* W = is_q ? qw : kw;
    const float* Bv = is_q ? qb : kb;
    const float* pool = (is_q ? g_xrow : g_xcol) + (size_t)b*CCH*L;
    float* out = (is_q ? g_qp : g_kp) + (size_t)b*CCH*L;
    for (int e = threadIdx.x; e < CCH*L; e += 256){
        int o = e / L, l = e - o*L;
        float a = Bv[o];
        for (int c = 0; c < CCH; c++)
            a = fmaf(W[o*CCH + c], pool[c*L + l], a);
        out[o*L + l] = a;
    }
}

// ---------------- per (b,c): exact corner max + Z ------------------------------------
__global__ void pam_stats_kernel(){
    __shared__ float sq[HH];
    __shared__ float sk[WW];
    const int bc = blockIdx.x;
    const int tid = threadIdx.x;
    for (int i = tid; i < HH; i += 256) sq[i] = g_qp[bc*HH + i];
    for (int i = tid; i < WW; i += 256) sk[i] = g_kp[bc*WW + i];
    __syncthreads();
    float qmx = -1e30f, qmn = 1e30f, kmx = -1e30f, kmn = 1e30f;
    for (int i = tid; i < HH; i += 256){ float v = sq[i]; qmx = fmaxf(qmx,v); qmn = fminf(qmn,v); }
    for (int i = tid; i < WW; i += 256){ float v = sk[i]; kmx = fmaxf(kmx,v); kmn = fminf(kmn,v); }
    qmx = block_max_256(qmx);
    qmn = -block_max_256(-qmn);
    kmx = block_max_256(kmx);
    kmn = -block_max_256(-kmn);
    // max over HW of qp[h]*kp[w] is attained at an extreme pair (exact)
    const float m = fmaxf(fmaxf(qmx*kmx, qmx*kmn), fmaxf(qmn*kmx, qmn*kmn));
    float z = 0.f;
    for (int i = tid; i < HWP; i += 256){
        int h = i / WW, w = i - h*WW;
        z += __expf(sq[h]*sk[w] - m);
    }
    z = block_sum_256(z);
    if (tid == 0){ g_m[bc] = m; g_z[bc] = z; }
}

// ---------------- fused v-GEMM + attention + residual -> d_out -----------------------
__global__ void __launch_bounds__(256) apply_kernel(
    const float* __restrict__ vw, const float* __restrict__ vb,
    const float* __restrict__ gamma, float* __restrict__ out)
{
    __shared__ __align__(16) float s_x[64*128];
    const int tid = threadIdx.x;
    const int b = blockIdx.y;
    const int px0 = blockIdx.x * 128;
    for (int e = tid; e < 2048; e += 256){
        int c = e >> 5; int p = (e & 31) * 4;
        *(float4*)&s_x[c*128 + p] = *(const float4*)&g_x[((size_t)(b*CCH + c))*HWP + px0 + p];
    }
    __syncthreads();
    const int co_slot = tid >> 5;
    const int ps = (tid & 31) * 4;
    float acc[8][4];
#pragma unroll
    for (int i = 0; i < 8; i++){ acc[i][0]=acc[i][1]=acc[i][2]=acc[i][3]=0.f; }
#pragma unroll 4
    for (int c = 0; c < 64; c++){
        float4 xv = *(const float4*)&s_x[c*128 + ps];
#pragma unroll
        for (int i = 0; i < 8; i++){
            float wv = vw[(co_slot*8+i)*64 + c];    // warp-uniform load
            acc[i][0] = fmaf(wv, xv.x, acc[i][0]);
            acc[i][1] = fmaf(wv, xv.y, acc[i][1]);
            acc[i][2] = fmaf(wv, xv.z, acc[i][2]);
            acc[i][3] = fmaf(wv, xv.w, acc[i][3]);
        }
    }
    const float gm = gamma[0];
#pragma unroll
    for (int i = 0; i < 8; i++){
        const int co = co_slot*8 + i;
        const int bc = b*CCH + co;
        const float bv = vb[co];
        const float mm = g_m[bc];
        const float iz = 1.f / g_z[bc];
        const float* qp = g_qp + bc*HH;
        const float* kp = g_kp + bc*WW;
#pragma unroll
        for (int j = 0; j < 4; j++){
            int px = px0 + ps + j;
            int h = px / WW, w = px - h*WW;
            float v = acc[i][j] + bv;
            float attn = __expf(qp[h]*kp[w] - mm) * iz;
            out[(size_t)bc*HWP + px] = fmaf(gm * v, attn, s_x[co*128 + ps + j]);
        }
    }
}

// ---------------- launch ---------------------------------------------------------------
extern "C" void kernel_launch(void* const* d_in, const int* in_sizes, int n_in,
                              void* d_out, int out_size) {
    const float* lidar    = (const float*)d_in[0];
    const float* guidance = (const float*)d_in[1];
    const float* illu     = (const float*)d_in[2];
    const float* conv_w   = (const float*)d_in[3];
    const float* tw       = (const float*)d_in[4];
    const float* tb       = (const float*)d_in[5];
    const float* bt_g     = (const float*)d_in[6];
    const float* bt_b     = (const float*)d_in[7];
    const float* bt_m     = (const float*)d_in[8];
    const float* bt_v     = (const float*)d_in[9];
    const float* rgbd_w   = (const float*)d_in[10];
    const float* rgbd_b   = (const float*)d_in[11];
    const float* br_g     = (const float*)d_in[12];
    const float* br_b     = (const float*)d_in[13];
    const float* br_m     = (const float*)d_in[14];
    const float* br_v     = (const float*)d_in[15];
    const float* q_w      = (const float*)d_in[16];
    const float* q_b      = (const float*)d_in[17];
    const float* k_w      = (const float*)d_in[18];
    const float* k_b      = (const float*)d_in[19];
    const float* v_w      = (const float*)d_in[20];
    const float* v_b      = (const float*)d_in[21];
    const float* pam_g    = (const float*)d_in[22];
    const float* theta    = (const float*)d_in[23];
    float* out = (float*)d_out;

    gate_kernel<<<BB*9, 256>>>(illu, tw, tb, bt_g, bt_b, bt_m, bt_v);
    prep_kernel<<<1, 256>>>(conv_w);

    // out_normal = conv3x3(guidance) -> g_on (written via device symbol)
    conv3x3_kernel<64, false><<<dim3(20, 10, 8), 256>>>(
        guidance, nullptr, conv_w, nullptr, nullptr, nullptr, nullptr, nullptr);

    fuse_weighted_kernel<<<NPIX/256, 256>>>();
    fuse_gemm_kernel<<<dim3(HWP/128, BB), 256>>>(theta);

    // x = relu(bn(conv3x3(cat(g_nn, lidar)))) -> g_x
    conv3x3_kernel<128, true><<<dim3(20, 10, 8), 256>>>(
        nullptr, lidar, rgbd_w, rgbd_b, br_g, br_b, br_m, br_v);

    rowmean_kernel<<<BB*CCH*HH/8, 256>>>();
    colmean_kernel<<<BB*CCH, WW>>>();
    qk_pool_kernel<<<dim3(BB, 2), 256>>>(q_w, q_b, k_w, k_b);
    pam_stats_kernel<<<BB*CCH, 256>>>();

    apply_kernel<<<dim3(HWP/128, BB), 256>>>(v_w, v_b, pam_g, out);
}

// round 17
// speedup vs baseline: 1.4491x; 1.4491x over previous
#include <cuda_runtime.h>
#include <math.h>

#define HH 160
#define WW 320
#define BB 4
#define CCH 64
#define HWP (HH*WW)            // 51200
#define NPIX (BB*CCH*HWP)      // 13107200
#define TH 80                  // tile rows per image
#define TW 160                 // tile cols per image
#define NT 12800               // tiles per image (TH*TW)

// ---------------- scratch: referenced ONLY inside device code -------------------
__device__ __align__(256) float g_on[NPIX];   // out_normal
__device__ __align__(256) float g_wt[NPIX];   // shift-weighted sum
__device__ __align__(256) float g_nn[NPIX];   // new_normal
__device__ __align__(256) float g_x [NPIX];   // conv_rgbd output
__device__ __align__(256) float g_V[104857600];   // Winograd input transform [64 planes][<=128 c][NT]
__device__ __align__(256) float g_M[52428800];    // Winograd GEMM output     [64 planes][64 o][NT]
__device__ float g_U1[16*64*64];    // transformed weights conv1 [(k*64+c)*64 + o]
__device__ float g_U2[16*128*64];   // transformed weights conv2 [(k*128+c)*64 + o]
__device__ float g_xrow[BB*CCH*HH];
__device__ float g_xcol[BB*CCH*WW];
__device__ float g_qp[BB*CCH*HH];
__device__ float g_kp[BB*CCH*WW];
__device__ float g_m[BB*CCH];
__device__ float g_z[BB*CCH];
__device__ float g_gate[BB*9];
__device__ float g_s[BB*9];
__device__ float g_kd[CCH*CCH];

// ---------------- block reductions (blockDim.x == 256) --------------------------
__device__ __forceinline__ float block_sum_256(float v){
    __shared__ float red[8];
    int tid = threadIdx.x;
#pragma unroll
    for (int o = 16; o > 0; o >>= 1) v += __shfl_xor_sync(0xffffffffu, v, o);
    __syncthreads();
    if ((tid & 31) == 0) red[tid >> 5] = v;
    __syncthreads();
    if (tid == 0){
        float r = 0.f;
#pragma unroll
        for (int i = 0; i < 8; i++) r += red[i];
        red[0] = r;
    }
    __syncthreads();
    return red[0];
}

__device__ __forceinline__ float block_max_256(float v){
    __shared__ float red[8];
    int tid = threadIdx.x;
#pragma unroll
    for (int o = 16; o > 0; o >>= 1) v = fmaxf(v, __shfl_xor_sync(0xffffffffu, v, o));
    __syncthreads();
    if ((tid & 31) == 0) red[tid >> 5] = v;
    __syncthreads();
    if (tid == 0){
        float r = red[0];
#pragma unroll
        for (int i = 1; i < 8; i++) r = fmaxf(r, red[i]);
        red[0] = r;
    }
    __syncthreads();
    return red[0];
}

// ---------------- illumination gate: conv s2 + BN + ReLU -> mean ----------------
__global__ void gate_kernel(const float* __restrict__ illu, const float* __restrict__ tw,
                            const float* __restrict__ tb, const float* __restrict__ bg,
                            const float* __restrict__ bbet, const float* __restrict__ bm,
                            const float* __restrict__ bv){
    const int bn = blockIdx.x;          // b*9+n
    const int b = bn / 9, n = bn % 9;
    const float* src = illu + (size_t)b * (2*HH) * (2*WW);
    float w9[9];
#pragma unroll
    for (int k = 0; k < 9; k++) w9[k] = tw[n*9+k];
    const float bias = tb[n];
    const float sc = bg[n] * rsqrtf(bv[n] + 1e-5f);
    const float sh = bbet[n] - bm[n]*sc;
    float acc = 0.f;
    for (int i = threadIdx.x; i < HWP; i += 256){
        int y = i / WW, x = i - y*WW;
        float c = bias;
#pragma unroll
        for (int ky = 0; ky < 3; ky++){
            int iy = 2*y + ky - 1;
            if ((unsigned)iy >= (unsigned)(2*HH)) continue;
#pragma unroll
            for (int kx = 0; kx < 3; kx++){
                int ix = 2*x + kx - 1;
                if ((unsigned)ix < (unsigned)(2*WW))
                    c = fmaf(src[(size_t)iy*(2*WW)+ix], w9[ky*3+kx], c);
            }
        }
        acc += fmaxf(c*sc + sh, 0.f);
    }
    float total = block_sum_256(acc);
    if (threadIdx.x == 0) g_gate[bn] = total * (1.f / HWP);
}

// ---------------- s normalization + kernel_diff ----------------------------------
__global__ void prep_kernel(const float* __restrict__ conv_w){
    int tid = threadIdx.x;
    if (tid < BB){
        float s = 0.f;
        for (int n = 0; n < 9; n++) s += fabsf(g_gate[tid*9+n]);
        float inv = 1.f / (s + 1e-8f);
        for (int n = 0; n < 9; n++) g_s[tid*9+n] = g_gate[tid*9+n] * inv;
    }
    for (int e = tid; e < CCH*CCH; e += 256){
        float a = 0.f;
#pragma unroll
        for (int k = 0; k < 9; k++) a += conv_w[e*9 + k];
        g_kd[e] = a;
    }
}

// ---------------- Winograd weight transform: U = G g G^T --------------------------
// stored transposed for coalesced GEMM staging: U[(k*CIN + c)*64 + o]
template<int CIN>
__global__ void wgt_transform(const float* __restrict__ wgt){
    const int idx = blockIdx.x * 256 + threadIdx.x;   // 64*CIN threads
    const int c = idx % CIN, o = idx / CIN;
    float g[3][3];
#pragma unroll
    for (int r = 0; r < 3; r++)
#pragma unroll
        for (int q = 0; q < 3; q++)
            g[r][q] = wgt[((size_t)o*CIN + c)*9 + r*3 + q];
    float u[4][3];
#pragma unroll
    for (int j = 0; j < 3; j++){
        u[0][j] = g[0][j];
        u[1][j] = 0.5f*(g[0][j] + g[1][j] + g[2][j]);
        u[2][j] = 0.5f*(g[0][j] - g[1][j] + g[2][j]);
        u[3][j] = g[2][j];
    }
    float* Ug = (CIN == 64) ? g_U1 : g_U2;
#pragma unroll
    for (int r = 0; r < 4; r++){
        float U0 = u[r][0];
        float U1 = 0.5f*(u[r][0] + u[r][1] + u[r][2]);
        float U2 = 0.5f*(u[r][0] - u[r][1] + u[r][2]);
        float U3 = u[r][2];
        Ug[((size_t)(r*4+0)*CIN + c)*64 + o] = U0;
        Ug[((size_t)(r*4+1)*CIN + c)*64 + o] = U1;
        Ug[((size_t)(r*4+2)*CIN + c)*64 + o] = U2;
        Ug[((size_t)(r*4+3)*CIN + c)*64 + o] = U3;
    }
}

// ---------------- Winograd input transform: V = B^T d B ---------------------------
// CIN=64: src = src0 (guidance). CIN=128: c<64 from g_nn, else from src1 (lidar).
// Writes g_V[((k*BB + b)*CIN + c)*NT + t], k = i*4+j.
template<int CIN>
__global__ void in_transform(const float* __restrict__ src0, const float* __restrict__ src1){
    const int idx = blockIdx.x * 256 + threadIdx.x;   // BB*CIN*NT threads
    const int t = idx % NT;
    int tmp = idx / NT;
    const int c = tmp % CIN;
    const int b = tmp / CIN;
    const int ti = t / TW, tj = t % TW;
    const float* sp;
    if (CIN == 128) sp = (c < CCH) ? (g_nn + ((size_t)(b*CCH + c))*HWP)
                                   : (src1 + ((size_t)(b*CCH + (c - CCH)))*HWP);
    else            sp = src0 + ((size_t)(b*CCH + c))*HWP;
    const int y0 = 2*ti - 1, x0 = 2*tj - 1;
    float d[4][4];
#pragma unroll
    for (int r = 0; r < 4; r++){
        int y = y0 + r;
        bool yin = ((unsigned)y < (unsigned)HH);
        const float* rp = sp + (size_t)y*WW;
#pragma unroll
        for (int q = 0; q < 4; q++){
            int x = x0 + q;
            d[r][q] = (yin && (unsigned)x < (unsigned)WW) ? rp[x] : 0.f;
        }
    }
    float tr[4][4];
#pragma unroll
    for (int j = 0; j < 4; j++){
        tr[0][j] = d[0][j] - d[2][j];
        tr[1][j] = d[1][j] + d[2][j];
        tr[2][j] = d[2][j] - d[1][j];
        tr[3][j] = d[1][j] - d[3][j];
    }
#pragma unroll
    for (int i = 0; i < 4; i++){
        float v0 = tr[i][0] - tr[i][2];
        float v1 = tr[i][1] + tr[i][2];
        float v2 = tr[i][2] - tr[i][1];
        float v3 = tr[i][1] - tr[i][3];
        g_V[((size_t)((i*4+0)*BB + b)*CIN + c)*NT + t] = v0;
        g_V[((size_t)((i*4+1)*BB + b)*CIN + c)*NT + t] = v1;
        g_V[((size_t)((i*4+2)*BB + b)*CIN + c)*NT + t] = v2;
        g_V[((size_t)((i*4+3)*BB + b)*CIN + c)*NT + t] = v3;
    }
}

// ---------------- Winograd GEMM: M[p] = U[k] @ V[p], p = k*BB+b --------------------
// block: 64 co x 256 tiles, K chunked by 32. smem 40KB.
template<int CIN>
__global__ void __launch_bounds__(256) gemm_wino(){
    __shared__ __align__(16) float s_v[32*256];
    __shared__ float s_u[32*64];
    const int tid = threadIdx.x;
    const int p = blockIdx.y;
    const int k = p >> 2;                 // BB == 4
    const int px0 = blockIdx.x * 256;
    const int wslot = tid >> 5;           // warp id 0..7 -> 8 co each
    const int ts0 = (tid & 31) * 4;
    const float* Ug = (CIN == 64) ? g_U1 : g_U2;
    float acc[8][8];
#pragma unroll
    for (int u = 0; u < 8; u++)
#pragma unroll
        for (int j = 0; j < 8; j++) acc[u][j] = 0.f;

    for (int cg = 0; cg < CIN/32; cg++){
#pragma unroll
        for (int i = 0; i < 8; i++){
            int e = tid + i*256;          // float4 index, 2048 total (32 rows x 64 f4)
            int cl = e >> 6; int col = (e & 63) * 4;
            *(float4*)&s_v[cl*256 + col] =
                *(const float4*)&g_V[((size_t)p*CIN + cg*32 + cl)*NT + px0 + col];
        }
#pragma unroll
        for (int i = 0; i < 8; i++){
            int e = tid + i*256;          // 2048 floats
            s_u[e] = Ug[((size_t)k*CIN + cg*32 + (e >> 6))*64 + (e & 63)];
        }
        __syncthreads();
#pragma unroll 4
        for (int c = 0; c < 32; c++){
            float4 v0 = *(const float4*)&s_v[c*256 + ts0];
            float4 v1 = *(const float4*)&s_v[c*256 + 128 + ts0];
#pragma unroll
            for (int u = 0; u < 8; u++){
                float wu = s_u[c*64 + wslot*8 + u];   // warp-uniform broadcast
                acc[u][0] = fmaf(wu, v0.x, acc[u][0]);
                acc[u][1] = fmaf(wu, v0.y, acc[u][1]);
                acc[u][2] = fmaf(wu, v0.z, acc[u][2]);
                acc[u][3] = fmaf(wu, v0.w, acc[u][3]);
                acc[u][4] = fmaf(wu, v1.x, acc[u][4]);
                acc[u][5] = fmaf(wu, v1.y, acc[u][5]);
                acc[u][6] = fmaf(wu, v1.z, acc[u][6]);
                acc[u][7] = fmaf(wu, v1.w, acc[u][7]);
            }
        }
        __syncthreads();
    }
#pragma unroll
    for (int u = 0; u < 8; u++){
        const int co = wslot*8 + u;
        size_t base = ((size_t)p*CCH + co)*NT + px0;
        float4 r0 = make_float4(acc[u][0], acc[u][1], acc[u][2], acc[u][3]);
        float4 r1 = make_float4(acc[u][4], acc[u][5], acc[u][6], acc[u][7]);
        *(float4*)&g_M[base + ts0]       = r0;
        *(float4*)&g_M[base + 128 + ts0] = r1;
    }
}

// ---------------- Winograd output transform: Y = A^T M A [+BN+ReLU] ----------------
template<bool EPI>
__global__ void out_transform(const float* __restrict__ bias, const float* __restrict__ bng,
                              const float* __restrict__ bnb, const float* __restrict__ bnm,
                              const float* __restrict__ bnv){
    const int idx = blockIdx.x * 256 + threadIdx.x;   // BB*64*NT threads
    const int t = idx % NT;
    int tmp = idx / NT;
    const int o = tmp % CCH;
    const int b = tmp / CCH;
    float m[4][4];
#pragma unroll
    for (int i = 0; i < 4; i++)
#pragma unroll
        for (int j = 0; j < 4; j++)
            m[i][j] = g_M[((size_t)((i*4+j)*BB + b)*CCH + o)*NT + t];
    float s0[4], s1[4];
#pragma unroll
    for (int j = 0; j < 4; j++){
        s0[j] = m[0][j] + m[1][j] + m[2][j];
        s1[j] = m[1][j] - m[2][j] - m[3][j];
    }
    float y00 = s0[0] + s0[1] + s0[2];
    float y01 = s0[1] - s0[2] - s0[3];
    float y10 = s1[0] + s1[1] + s1[2];
    float y11 = s1[1] - s1[2] - s1[3];
    if (EPI){
        float sc = bng[o] * rsqrtf(bnv[o] + 1e-5f);
        float sh = (bias[o] - bnm[o]) * sc + bnb[o];
        y00 = fmaxf(y00*sc + sh, 0.f);
        y01 = fmaxf(y01*sc + sh, 0.f);
        y10 = fmaxf(y10*sc + sh, 0.f);
        y11 = fmaxf(y11*sc + sh, 0.f);
    }
    const int ti = t / TW, tj = t % TW;
    float* outp = EPI ? g_x : g_on;
    size_t base = ((size_t)(b*CCH + o))*HWP + (size_t)(2*ti)*WW + 2*tj;
    outp[base]      = y00;
    outp[base+1]    = y01;
    outp[base+WW]   = y10;
    outp[base+WW+1] = y11;
}

// ---------------- weighted = sum_n s_n * reflect-shift_n(out_normal) --------------
__global__ void fuse_weighted_kernel(){
    __shared__ float ss[9];
    const int idx = blockIdx.x * 256 + threadIdx.x;
    const int b = idx / (CCH*HWP);       // block-uniform (256 | C*HW)
    if (threadIdx.x < 9) ss[threadIdx.x] = g_s[b*9 + threadIdx.x];
    __syncthreads();
    const int w = idx % WW;
    const int t = idx / WW;
    const int h = t % HH;
    const int bc = t / HH;
    const float* base = g_on + (size_t)bc*HWP;
    float a = 0.f;
#pragma unroll
    for (int n = 0; n < 9; n++){
        int dy = n/3 - 1, dx = n%3 - 1;
        int y = h + dy; y = (y < 0) ? 1 : ((y >= HH) ? HH-2 : y);
        int x = w + dx; x = (x < 0) ? 1 : ((x >= WW) ? WW-2 : x);
        a = fmaf(ss[n], base[y*WW + x], a);
    }
    g_wt[idx] = a;
}

// ---------------- new_normal = out_normal - theta * (kd @ weighted) ----------------
__global__ void __launch_bounds__(256) fuse_gemm_kernel(const float* __restrict__ theta){
    __shared__ __align__(16) float s_t[64*128];
    const int tid = threadIdx.x;
    const int b = blockIdx.y;
    const int px0 = blockIdx.x * 128;
    for (int e = tid; e < 2048; e += 256){
        int c = e >> 5; int p = (e & 31) * 4;
        *(float4*)&s_t[c*128 + p] = *(const float4*)&g_wt[((size_t)(b*CCH + c))*HWP + px0 + p];
    }
    __syncthreads();
    const int co_slot = tid >> 5;
    const int ps = (tid & 31) * 4;
    float acc[8][4];
#pragma unroll
    for (int i = 0; i < 8; i++){ acc[i][0]=acc[i][1]=acc[i][2]=acc[i][3]=0.f; }
#pragma unroll 4
    for (int c = 0; c < 64; c++){
        float4 wv = *(const float4*)&s_t[c*128 + ps];
#pragma unroll
        for (int i = 0; i < 8; i++){
            float kv = g_kd[(co_slot*8+i)*64 + c];
            acc[i][0] = fmaf(kv, wv.x, acc[i][0]);
            acc[i][1] = fmaf(kv, wv.y, acc[i][1]);
            acc[i][2] = fmaf(kv, wv.z, acc[i][2]);
            acc[i][3] = fmaf(kv, wv.w, acc[i][3]);
        }
    }
    const float th = theta[0];
#pragma unroll
    for (int i = 0; i < 8; i++){
        int co = co_slot*8 + i;
        size_t base = ((size_t)(b*CCH + co))*HWP + px0 + ps;
        float4 ov = *(const float4*)&g_on[base];
        float4 r;
        r.x = ov.x - th*acc[i][0];
        r.y = ov.y - th*acc[i][1];
        r.z = ov.z - th*acc[i][2];
        r.w = ov.w - th*acc[i][3];
        *(float4*)&g_nn[base] = r;
    }
}

// ---------------- pooled means of x -------------------------------------------------
__global__ void rowmean_kernel(){
    int r = blockIdx.x * 8 + (threadIdx.x >> 5);
    int lane = threadIdx.x & 31;
    const float* p = g_x + (size_t)r * WW;
    float s = 0.f;
#pragma unroll
    for (int i = 0; i < 10; i++) s += p[lane + i*32];
#pragma unroll
    for (int o = 16; o > 0; o >>= 1) s += __shfl_xor_sync(0xffffffffu, s, o);
    if (lane == 0) g_xrow[r] = s * (1.f / WW);
}

__global__ void colmean_kernel(){
    int bc = blockIdx.x;
    int w = threadIdx.x;
    const float* p = g_x + (size_t)bc * HWP + w;
    float s = 0.f;
    for (int h = 0; h < HH; h++) s += p[h*WW];
    g_xcol[bc*WW + w] = s * (1.f / HH);
}

// ---------------- pooled q/k projections --------------------------------------------
__global__ void qk_pool_kernel(const float* __restrict__ qw, const float* __restrict__ qb,
                               const float* __restrict__ kw, const float* __restrict__ kb){
    const int b = blockIdx.x;
    const bool is_q = (blockIdx.y == 0);
    const int L = is_q ? HH : WW;
    const float* W = is_q ? qw : kw;
    const float* Bv = is_q ? qb : kb;
    const float* pool = (is_q ? g_xrow : g_xcol) + (size_t)b*CCH*L;
    float* out = (is_q ? g_qp : g_kp) + (size_t)b*CCH*L;
    for (int e = threadIdx.x; e < CCH*L; e += 256){
        int o = e / L, l = e - o*L;
        float a = Bv[o];
        for (int c = 0; c < CCH; c++)
            a = fmaf(W[o*CCH + c], pool[c*L + l], a);
        out[o*L + l] = a;
    }
}

// ---------------- per (b,c): exact corner max + Z ------------------------------------
__global__ void pam_stats_kernel(){
    __shared__ float sq[HH];
    __shared__ float sk[WW];
    const int bc = blockIdx.x;
    const int tid = threadIdx.x;
    for (int i = tid; i < HH; i += 256) sq[i] = g_qp[bc*HH + i];
    for (int i = tid; i < WW; i += 256) sk[i] = g_kp[bc*WW + i];
    __syncthreads();
    float qmx = -1e30f, qmn = 1e30f, kmx = -1e30f, kmn = 1e30f;
    for (int i = tid; i < HH; i += 256){ float v = sq[i]; qmx = fmaxf(qmx,v); qmn = fminf(qmn,v); }
    for (int i = tid; i < WW; i += 256){ float v = sk[i]; kmx = fmaxf(kmx,v); kmn = fminf(kmn,v); }
    qmx = block_max_256(qmx);
    qmn = -block_max_256(-qmn);
    kmx = block_max_256(kmx);
    kmn = -block_max_256(-kmn);
    const float m = fmaxf(fmaxf(qmx*kmx, qmx*kmn), fmaxf(qmn*kmx, qmn*kmn));
    float z = 0.f;
    for (int i = tid; i < HWP; i += 256){
        int h = i / WW, w = i - h*WW;
        z += __expf(sq[h]*sk[w] - m);
    }
    z = block_sum_256(z);
    if (tid == 0){ g_m[bc] = m; g_z[bc] = z; }
}

// ---------------- fused v-GEMM + attention + residual -> d_out -----------------------
__global__ void __launch_bounds__(256) apply_kernel(
    const float* __restrict__ vw, const float* __restrict__ vb,
    const float* __restrict__ gamma, float* __restrict__ out)
{
    __shared__ __align__(16) float s_x[64*128];
    const int tid = threadIdx.x;
    const int b = blockIdx.y;
    const int px0 = blockIdx.x * 128;
    for (int e = tid; e < 2048; e += 256){
        int c = e >> 5; int p = (e & 31) * 4;
        *(float4*)&s_x[c*128 + p] = *(const float4*)&g_x[((size_t)(b*CCH + c))*HWP + px0 + p];
    }
    __syncthreads();
    const int co_slot = tid >> 5;
    const int ps = (tid & 31) * 4;
    float acc[8][4];
#pragma unroll
    for (int i = 0; i < 8; i++){ acc[i][0]=acc[i][1]=acc[i][2]=acc[i][3]=0.f; }
#pragma unroll 4
    for (int c = 0; c < 64; c++){
        float4 xv = *(const float4*)&s_x[c*128 + ps];
#pragma unroll
        for (int i = 0; i < 8; i++){
            float wv = vw[(co_slot*8+i)*64 + c];
            acc[i][0] = fmaf(wv, xv.x, acc[i][0]);
            acc[i][1] = fmaf(wv, xv.y, acc[i][1]);
            acc[i][2] = fmaf(wv, xv.z, acc[i][2]);
            acc[i][3] = fmaf(wv, xv.w, acc[i][3]);
        }
    }
    const float gm = gamma[0];
#pragma unroll
    for (int i = 0; i < 8; i++){
        const int co = co_slot*8 + i;
        const int bc = b*CCH + co;
        const float bv = vb[co];
        const float mm = g_m[bc];
        const float iz = 1.f / g_z[bc];
        const float* qp = g_qp + bc*HH;
        const float* kp = g_kp + bc*WW;
#pragma unroll
        for (int j = 0; j < 4; j++){
            int px = px0 + ps + j;
            int h = px / WW, w = px - h*WW;
            float v = acc[i][j] + bv;
            float attn = __expf(qp[h]*kp[w] - mm) * iz;
            out[(size_t)bc*HWP + px] = fmaf(gm * v, attn, s_x[co*128 + ps + j]);
        }
    }
}

// ---------------- launch ---------------------------------------------------------------
extern "C" void kernel_launch(void* const* d_in, const int* in_sizes, int n_in,
                              void* d_out, int out_size) {
    const float* lidar    = (const float*)d_in[0];
    const float* guidance = (const float*)d_in[1];
    const float* illu     = (const float*)d_in[2];
    const float* conv_w   = (const float*)d_in[3];
    const float* tw       = (const float*)d_in[4];
    const float* tb       = (const float*)d_in[5];
    const float* bt_g     = (const float*)d_in[6];
    const float* bt_b     = (const float*)d_in[7];
    const float* bt_m     = (const float*)d_in[8];
    const float* bt_v     = (const float*)d_in[9];
    const float* rgbd_w   = (const float*)d_in[10];
    const float* rgbd_b   = (const float*)d_in[11];
    const float* br_g     = (const float*)d_in[12];
    const float* br_b     = (const float*)d_in[13];
    const float* br_m     = (const float*)d_in[14];
    const float* br_v     = (const float*)d_in[15];
    const float* q_w      = (const float*)d_in[16];
    const float* q_b      = (const float*)d_in[17];
    const float* k_w      = (const float*)d_in[18];
    const float* k_b      = (const float*)d_in[19];
    const float* v_w      = (const float*)d_in[20];
    const float* v_b      = (const float*)d_in[21];
    const float* pam_g    = (const float*)d_in[22];
    const float* theta    = (const float*)d_in[23];
    float* out = (float*)d_out;

    gate_kernel<<<BB*9, 256>>>(illu, tw, tb, bt_g, bt_b, bt_m, bt_v);
    prep_kernel<<<1, 256>>>(conv_w);
    wgt_transform<64><<<(64*64)/256, 256>>>(conv_w);
    wgt_transform<128><<<(64*128)/256, 256>>>(rgbd_w);

    // conv1 via Winograd: guidance -> g_on
    in_transform<64><<<(BB*64*NT)/256, 256>>>(guidance, nullptr);
    gemm_wino<64><<<dim3(NT/256, 64), 256>>>();
    out_transform<false><<<(BB*CCH*NT)/256, 256>>>(nullptr, nullptr, nullptr, nullptr, nullptr);

    // fuse: shift-weighted sum + 1x1 diff GEMM -> g_nn
    fuse_weighted_kernel<<<NPIX/256, 256>>>();
    fuse_gemm_kernel<<<dim3(HWP/128, BB), 256>>>(theta);

    // conv2 via Winograd: cat(g_nn, lidar) -> g_x (BN+ReLU in output transform)
    in_transform<128><<<(BB*128*NT)/256, 256>>>(nullptr, lidar);
    gemm_wino<128><<<dim3(NT/256, 64), 256>>>();
    out_transform<true><<<(BB*CCH*NT)/256, 256>>>(rgbd_b, br_g, br_b, br_m, br_v);

    // PAM pooled path
    rowmean_kernel<<<BB*CCH*HH/8, 256>>>();
    colmean_kernel<<<BB*CCH, WW>>>();
    qk_pool_kernel<<<dim3(BB, 2), 256>>>(q_w, q_b, k_w, k_b);
    pam_stats_kernel<<<BB*CCH, 256>>>();

    // fused v + attention + residual
    apply_kernel<<<dim3(HWP/128, BB), 256>>>(v_w, v_b, pam_g, out);
}